// round 1
// baseline (speedup 1.0000x reference)
#include <cuda_runtime.h>

#define Nn   100000
#define Ee   1000000
#define FIN  128
#define HID  64
#define OUTF 40
#define NL   4
#define ALPHAc 0.5f
#define EPSBN  1e-5f

// ---------------- scratch (static device globals; no runtime alloc) --------
__device__ float g_h0[Nn * HID];
__device__ float g_hprev[Nn * HID];
__device__ float g_support[Nn * HID];
__device__ float g_agg[Nn * HID];     // holds `initial` then += scatter, then y
__device__ float g_dinv[Nn];          // deg accumulator, then deg^-1/2
__device__ float g_stats[2 * HID];    // per-feature sum, sumsq
__device__ int   g_is64;              // edge_index dtype flag

// ---------------- edge index access (int32 vs int64 defensive) -------------
__device__ __forceinline__ int edge_at(const void* ei, int is64, int idx) {
    if (is64) return (int)((const long long*)ei)[idx];
    return ((const int*)ei)[idx];
}

__global__ void k_detect(const void* ei) {
    // If data is really int32 pairs, reading as int64 combines two random
    // indices in [0,1e5): value = a + b*2^32 which is >= Nn unless b==0.
    // Check 8 values => false positive probability ~ (1e-5)^8.
    const long long* p = (const long long*)ei;
    int ok = 1;
    for (int i = 0; i < 8; i++) {
        long long v = p[i];
        if (v < 0 || v >= Nn) ok = 0;
    }
    g_is64 = ok;
}

// ---------------- gcn_norm ---------------------------------------------------
__global__ void k_zero_dinv() {
    int i = blockIdx.x * blockDim.x + threadIdx.x;
    if (i < Nn) g_dinv[i] = 0.0f;
}

__global__ void k_deg(const void* ei) {
    int e = blockIdx.x * blockDim.x + threadIdx.x;
    if (e < Ee) {
        int c = edge_at(ei, g_is64, Ee + e);
        atomicAdd(&g_dinv[c], 1.0f);
    }
}

__global__ void k_dinv_final() {
    int i = blockIdx.x * blockDim.x + threadIdx.x;
    if (i < Nn) g_dinv[i] = rsqrtf(g_dinv[i] + 1.0f);  // +1 self loop; deg>=1
}

// ---------------- input GEMM: h = relu(x @ Wi + bi) -------------------------
__global__ __launch_bounds__(256) void k_ingemm(const float* __restrict__ x,
                                                const float* __restrict__ Wi,
                                                const float* __restrict__ bi) {
    __shared__ float Ws[FIN * HID];   // 32 KB
    __shared__ float bs[HID];
    __shared__ float xs[4][FIN];      // 2 KB
    int tid = threadIdx.x;
    for (int i = tid; i < FIN * HID; i += 256) Ws[i] = Wi[i];
    if (tid < HID) bs[tid] = bi[tid];
    __syncthreads();
    int f = tid & 63, rl = tid >> 6;
    int rowBase = blockIdx.x * 64;
    for (int chunk = 0; chunk < 16; chunk++) {
        int r0 = rowBase + chunk * 4;
        for (int i = tid; i < 4 * FIN; i += 256) {
            int rr = i >> 7, kk = i & 127;
            int gr = r0 + rr;
            xs[rr][kk] = (gr < Nn) ? x[gr * FIN + kk] : 0.0f;
        }
        __syncthreads();
        int gr = r0 + rl;
        if (gr < Nn) {
            float acc = bs[f];
            #pragma unroll
            for (int k = 0; k < FIN; k++) acc += xs[rl][k] * Ws[k * HID + f];
            float h = fmaxf(acc, 0.0f);
            g_h0[gr * HID + f] = h;
            g_hprev[gr * HID + f] = h;
        }
        __syncthreads();
    }
}

// ------- fused layer GEMM: support = hp + hp@W1 ; agg = a*h0 + h0@W2 --------
__global__ __launch_bounds__(256) void k_layergemm(const float* __restrict__ W1,
                                                   const float* __restrict__ W2) {
    __shared__ float W1s[HID * HID];  // 16 KB
    __shared__ float W2s[HID * HID];  // 16 KB
    __shared__ float hp[4][HID];
    __shared__ float h0s[4][HID];
    int tid = threadIdx.x;
    for (int i = tid; i < HID * HID; i += 256) { W1s[i] = W1[i]; W2s[i] = W2[i]; }
    __syncthreads();
    int f = tid & 63, rl = tid >> 6;
    int rowBase = blockIdx.x * 64;
    for (int chunk = 0; chunk < 16; chunk++) {
        int gr = rowBase + chunk * 4 + rl;
        if (gr < Nn) {
            hp[rl][f]  = g_hprev[gr * HID + f];
            h0s[rl][f] = g_h0[gr * HID + f];
        }
        __syncthreads();
        if (gr < Nn) {
            float a1 = hp[rl][f];
            float a2 = ALPHAc * h0s[rl][f];
            #pragma unroll
            for (int k = 0; k < HID; k++) {
                a1 += hp[rl][k]  * W1s[k * HID + f];
                a2 += h0s[rl][k] * W2s[k * HID + f];
            }
            g_support[gr * HID + f] = a1;
            g_agg[gr * HID + f]     = a2;   // initial; scatter accumulates on top
        }
        __syncthreads();
    }
}

// ---------------- scatter: agg[col] += dinv[r]*dinv[c]*support[row] ---------
__global__ __launch_bounds__(256) void k_scatter(const void* __restrict__ ei) {
    int idx = blockIdx.x * 256 + threadIdx.x;
    int e = idx >> 6;
    int f = idx & 63;
    if (e < Ee) {
        int is64 = g_is64;
        int r = edge_at(ei, is64, e);
        int c = edge_at(ei, is64, Ee + e);
        float w = g_dinv[r] * g_dinv[c];
        atomicAdd(&g_agg[c * HID + f], w * g_support[r * HID + f]);
    }
}

// ---------------- BN stats ---------------------------------------------------
__global__ void k_zero_stats() {
    int i = threadIdx.x;
    if (i < 2 * HID) g_stats[i] = 0.0f;
}

// y = agg + dinv^2*support (self loop); accumulate per-feature sum/sumsq
__global__ __launch_bounds__(256) void k_combine() {
    __shared__ float s_sum[256];
    __shared__ float s_sq[256];
    int tid = threadIdx.x;
    int f = tid & 63, rl = tid >> 6;
    float lsum = 0.0f, lsq = 0.0f;
    for (int r = blockIdx.x * 4 + rl; r < Nn; r += gridDim.x * 4) {
        float d = g_dinv[r];
        float y = g_agg[r * HID + f] + d * d * g_support[r * HID + f];
        g_agg[r * HID + f] = y;
        lsum += y;
        lsq  += y * y;
    }
    s_sum[tid] = lsum;
    s_sq[tid]  = lsq;
    __syncthreads();
    if (rl == 0) {
        float a = s_sum[f] + s_sum[64 + f] + s_sum[128 + f] + s_sum[192 + f];
        float b = s_sq[f]  + s_sq[64 + f]  + s_sq[128 + f]  + s_sq[192 + f];
        atomicAdd(&g_stats[f], a);
        atomicAdd(&g_stats[HID + f], b);
    }
}

// hprev += relu(gamma*(y-m)*rsqrt(v+eps)+beta)
__global__ __launch_bounds__(256) void k_bnapply(const float* __restrict__ gamma,
                                                 const float* __restrict__ beta) {
    __shared__ float sc[HID];
    __shared__ float sh[HID];
    int tid = threadIdx.x;
    if (tid < HID) {
        float m = g_stats[tid] * (1.0f / Nn);
        float v = g_stats[HID + tid] * (1.0f / Nn) - m * m;
        float inv = rsqrtf(v + EPSBN);
        float scale = gamma[tid] * inv;
        sc[tid] = scale;
        sh[tid] = beta[tid] - m * scale;
    }
    __syncthreads();
    const int total = Nn * HID;
    for (int idx = blockIdx.x * 256 + tid; idx < total; idx += gridDim.x * 256) {
        int f = idx & 63;
        float o = g_agg[idx] * sc[f] + sh[f];
        g_hprev[idx] += fmaxf(o, 0.0f);
    }
}

// ---------------- output GEMM: out = hprev @ Wo + bo ------------------------
__global__ __launch_bounds__(256) void k_outgemm(const float* __restrict__ Wo,
                                                 const float* __restrict__ bo,
                                                 float* __restrict__ out) {
    __shared__ float Ws[HID * OUTF];  // 10 KB
    __shared__ float bs[OUTF];
    __shared__ float hp[32][HID];     // 8 KB
    int tid = threadIdx.x;
    for (int i = tid; i < HID * OUTF; i += 256) Ws[i] = Wo[i];
    if (tid < OUTF) bs[tid] = bo[tid];
    __syncthreads();
    int rowBase = blockIdx.x * 32;
    for (int i = tid; i < 32 * HID; i += 256) {
        int rr = i >> 6, kk = i & 63;
        int gr = rowBase + rr;
        hp[rr][kk] = (gr < Nn) ? g_hprev[gr * HID + kk] : 0.0f;
    }
    __syncthreads();
    for (int idx = tid; idx < 32 * OUTF; idx += 256) {
        int rr = idx / OUTF, f = idx % OUTF;
        int gr = rowBase + rr;
        if (gr >= Nn) continue;
        float acc = bs[f];
        #pragma unroll
        for (int k = 0; k < HID; k++) acc += hp[rr][k] * Ws[k * OUTF + f];
        out[gr * OUTF + f] = acc;
    }
}

// ---------------- launch ------------------------------------------------------
extern "C" void kernel_launch(void* const* d_in, const int* in_sizes, int n_in,
                              void* d_out, int out_size) {
    const float* x     = (const float*)d_in[0];
    const void*  ei    = d_in[1];
    const float* Wi    = (const float*)d_in[2];
    const float* bi    = (const float*)d_in[3];
    const float* w1    = (const float*)d_in[4];
    const float* w2    = (const float*)d_in[5];
    const float* gamma = (const float*)d_in[6];
    const float* beta  = (const float*)d_in[7];
    const float* Wo    = (const float*)d_in[8];
    const float* bo    = (const float*)d_in[9];
    float* out = (float*)d_out;

    k_detect<<<1, 1>>>(ei);
    k_zero_dinv<<<(Nn + 255) / 256, 256>>>();
    k_deg<<<(Ee + 255) / 256, 256>>>(ei);
    k_dinv_final<<<(Nn + 255) / 256, 256>>>();

    k_ingemm<<<(Nn + 63) / 64, 256>>>(x, Wi, bi);

    for (int l = 0; l < NL; l++) {
        k_zero_stats<<<1, 128>>>();
        k_layergemm<<<(Nn + 63) / 64, 256>>>(w1 + l * HID * HID, w2 + l * HID * HID);
        k_scatter<<<(Ee * 64) / 256, 256>>>(ei);
        k_combine<<<512, 256>>>();
        k_bnapply<<<512, 256>>>(gamma + l * HID, beta + l * HID);
    }

    k_outgemm<<<(Nn + 31) / 32, 256>>>(Wo, bo, out);
}

// round 2
// speedup vs baseline: 2.0178x; 2.0178x over previous
#include <cuda_runtime.h>

#define Nn   100000
#define Ee   1000000
#define FIN  128
#define HID  64
#define OUTF 40
#define NL   4
#define ALPHAc 0.5f
#define EPSBN  1e-5f

// ---------------- scratch (static device globals) ---------------------------
__device__ __align__(16) float g_h0[Nn * HID];
__device__ __align__(16) float g_hprev[Nn * HID];
__device__ __align__(16) float g_support[Nn * HID];
__device__ __align__(16) float g_agg[Nn * HID];
__device__ float g_dinv[Nn];
__device__ float g_stats[2 * HID];
__device__ int   g_is64;
__device__ __align__(16) int4 g_edges[Ee];   // {row*HID, col*HID, w_bits, 0}

// ---------------- edge index access (int32 vs int64 defensive) -------------
__device__ __forceinline__ int edge_at(const void* ei, int is64, int idx) {
    if (is64) return (int)((const long long*)ei)[idx];
    return ((const int*)ei)[idx];
}

// detect dtype + zero dinv in one kernel
__global__ void k_detect_zero(const void* ei) {
    int i = blockIdx.x * blockDim.x + threadIdx.x;
    if (i == 0) {
        const long long* p = (const long long*)ei;
        int ok = 1;
        for (int j = 0; j < 8; j++) {
            long long v = p[j];
            if (v < 0 || v >= Nn) ok = 0;
        }
        g_is64 = ok;
    }
    if (i < Nn) g_dinv[i] = 0.0f;
}

__global__ void k_deg(const void* ei) {
    int e = blockIdx.x * blockDim.x + threadIdx.x;
    if (e < Ee) {
        int c = edge_at(ei, g_is64, Ee + e);
        atomicAdd(&g_dinv[c], 1.0f);
    }
}

__global__ void k_dinv_final() {
    int i = blockIdx.x * blockDim.x + threadIdx.x;
    if (i < Nn) g_dinv[i] = rsqrtf(g_dinv[i] + 1.0f);
}

// pack edges: indices premultiplied by HID, weight precomputed
__global__ void k_prep(const void* __restrict__ ei) {
    int e = blockIdx.x * blockDim.x + threadIdx.x;
    if (e < Ee) {
        int is64 = g_is64;
        int r = edge_at(ei, is64, e);
        int c = edge_at(ei, is64, Ee + e);
        float w = g_dinv[r] * g_dinv[c];
        g_edges[e] = make_int4(r * HID, c * HID, __float_as_int(w), 0);
    }
}

// ---------------- input GEMM: h = relu(x @ Wi + bi) -------------------------
__global__ __launch_bounds__(256) void k_ingemm(const float* __restrict__ x,
                                                const float* __restrict__ Wi,
                                                const float* __restrict__ bi) {
    __shared__ float Ws[FIN * HID];   // 32 KB
    __shared__ float bs[HID];
    __shared__ float xs[4][FIN];
    int tid = threadIdx.x;
    for (int i = tid; i < FIN * HID; i += 256) Ws[i] = Wi[i];
    if (tid < HID) bs[tid] = bi[tid];
    __syncthreads();
    int f = tid & 63, rl = tid >> 6;
    int rowBase = blockIdx.x * 64;
    for (int chunk = 0; chunk < 16; chunk++) {
        int r0 = rowBase + chunk * 4;
        for (int i = tid; i < 4 * FIN / 4; i += 256) {
            int rr = i >> 5, q = i & 31;
            int gr = r0 + rr;
            float4 v = make_float4(0.f, 0.f, 0.f, 0.f);
            if (gr < Nn) v = *(const float4*)(x + gr * FIN + q * 4);
            *(float4*)(&xs[rr][q * 4]) = v;
        }
        __syncthreads();
        int gr = r0 + rl;
        if (gr < Nn) {
            float acc = bs[f];
            #pragma unroll
            for (int k = 0; k < FIN; k++) acc += xs[rl][k] * Ws[k * HID + f];
            float h = fmaxf(acc, 0.0f);
            g_h0[gr * HID + f] = h;
            g_hprev[gr * HID + f] = h;
        }
        __syncthreads();
    }
}

// ------- fused layer GEMM: support = hp + hp@W1 ; agg = a*h0 + h0@W2 --------
// 16-row tiles, 4 rows per thread (register accumulators).
__global__ __launch_bounds__(256) void k_layergemm(const float* __restrict__ W1,
                                                   const float* __restrict__ W2) {
    __shared__ float W1s[HID * HID];  // 16 KB
    __shared__ float W2s[HID * HID];  // 16 KB
    __shared__ float hp[16][HID];     // 4 KB
    __shared__ float h0s[16][HID];    // 4 KB
    int tid = threadIdx.x;
    if (blockIdx.x == 0 && tid < 2 * HID) g_stats[tid] = 0.0f;
    for (int i = tid; i < HID * HID; i += 256) { W1s[i] = W1[i]; W2s[i] = W2[i]; }
    __syncthreads();
    int f = tid & 63, g = tid >> 6;   // g in 0..3, rows g*4..g*4+3
    const int ntiles = Nn / 16;       // 6250 exact
    for (int tile = blockIdx.x; tile < ntiles; tile += gridDim.x) {
        int rowBase = tile * 16;
        // load tiles (float4)
        for (int i = tid; i < 16 * 16; i += 256) {
            int rr = i >> 4, q = (i & 15) * 4;
            *(float4*)(&hp[rr][q])  = *(const float4*)(g_hprev + (rowBase + rr) * HID + q);
            *(float4*)(&h0s[rr][q]) = *(const float4*)(g_h0    + (rowBase + rr) * HID + q);
        }
        __syncthreads();
        float a1[4], a2[4];
        #pragma unroll
        for (int i = 0; i < 4; i++) {
            int rr = g * 4 + i;
            a1[i] = hp[rr][f];
            a2[i] = ALPHAc * h0s[rr][f];
        }
        #pragma unroll 4
        for (int k = 0; k < HID; k++) {
            float w1k = W1s[k * HID + f];
            float w2k = W2s[k * HID + f];
            #pragma unroll
            for (int i = 0; i < 4; i++) {
                int rr = g * 4 + i;
                a1[i] = fmaf(hp[rr][k],  w1k, a1[i]);
                a2[i] = fmaf(h0s[rr][k], w2k, a2[i]);
            }
        }
        #pragma unroll
        for (int i = 0; i < 4; i++) {
            int gr = rowBase + g * 4 + i;
            g_support[gr * HID + f] = a1[i];
            g_agg[gr * HID + f]     = a2[i];
        }
        __syncthreads();
    }
}

// ---------------- scatter: agg[col] += w * support[row], vectorized --------
__global__ __launch_bounds__(256) void k_scatter() {
    int idx = blockIdx.x * 256 + threadIdx.x;
    int e = idx >> 4;               // 16 threads per edge
    if (e >= Ee) return;
    int q = (idx & 15) << 2;        // feature quad
    int4 ed = g_edges[e];           // broadcast within the 16-thread group
    float w = __int_as_float(ed.z);
    float4 s = __ldg((const float4*)(g_support + ed.x + q));
    float* dst = g_agg + ed.y + q;
    asm volatile("red.global.add.v4.f32 [%0], {%1, %2, %3, %4};"
                 :: "l"(dst), "f"(w * s.x), "f"(w * s.y), "f"(w * s.z), "f"(w * s.w)
                 : "memory");
}

// ---- combine self-loop + compute BN stats (float4) --------------------------
__global__ __launch_bounds__(256) void k_combine() {
    __shared__ float4 s_sum[256];
    __shared__ float4 s_sq[256];
    int tid = threadIdx.x;
    int q  = tid & 15;    // feature quad: features q*4 .. q*4+3
    int rl = tid >> 4;    // 0..15
    float4 lsum = make_float4(0.f, 0.f, 0.f, 0.f);
    float4 lsq  = make_float4(0.f, 0.f, 0.f, 0.f);
    for (int r = blockIdx.x * 16 + rl; r < Nn; r += gridDim.x * 16) {
        float d = g_dinv[r];
        float w = d * d;
        float4 a = *(float4*)(g_agg + r * HID + q * 4);
        float4 s = *(const float4*)(g_support + r * HID + q * 4);
        float4 y = make_float4(fmaf(w, s.x, a.x), fmaf(w, s.y, a.y),
                               fmaf(w, s.z, a.z), fmaf(w, s.w, a.w));
        *(float4*)(g_agg + r * HID + q * 4) = y;
        lsum.x += y.x; lsum.y += y.y; lsum.z += y.z; lsum.w += y.w;
        lsq.x += y.x * y.x; lsq.y += y.y * y.y; lsq.z += y.z * y.z; lsq.w += y.w * y.w;
    }
    s_sum[tid] = lsum; s_sq[tid] = lsq;
    __syncthreads();
    for (int s = 128; s >= 16; s >>= 1) {
        if (tid < s) {
            float4 a = s_sum[tid], b = s_sum[tid + s];
            s_sum[tid] = make_float4(a.x + b.x, a.y + b.y, a.z + b.z, a.w + b.w);
            float4 c = s_sq[tid], d = s_sq[tid + s];
            s_sq[tid] = make_float4(c.x + d.x, c.y + d.y, c.z + d.z, c.w + d.w);
        }
        __syncthreads();
    }
    if (tid < 16) {
        float4 a = s_sum[tid], b = s_sq[tid];
        atomicAdd(&g_stats[tid * 4 + 0], a.x);
        atomicAdd(&g_stats[tid * 4 + 1], a.y);
        atomicAdd(&g_stats[tid * 4 + 2], a.z);
        atomicAdd(&g_stats[tid * 4 + 3], a.w);
        atomicAdd(&g_stats[HID + tid * 4 + 0], b.x);
        atomicAdd(&g_stats[HID + tid * 4 + 1], b.y);
        atomicAdd(&g_stats[HID + tid * 4 + 2], b.z);
        atomicAdd(&g_stats[HID + tid * 4 + 3], b.w);
    }
}

// hprev += relu(gamma*(y-m)*rsqrt(v+eps)+beta), float4
__global__ __launch_bounds__(256) void k_bnapply(const float* __restrict__ gamma,
                                                 const float* __restrict__ beta) {
    __shared__ float4 sc[16];
    __shared__ float4 sh[16];
    int tid = threadIdx.x;
    if (tid < HID) {
        float m = g_stats[tid] * (1.0f / Nn);
        float v = g_stats[HID + tid] * (1.0f / Nn) - m * m;
        float inv = rsqrtf(v + EPSBN);
        float scale = gamma[tid] * inv;
        ((float*)sc)[tid] = scale;
        ((float*)sh)[tid] = beta[tid] - m * scale;
    }
    __syncthreads();
    const int total4 = Nn * (HID / 4);
    for (int idx = blockIdx.x * 256 + tid; idx < total4; idx += gridDim.x * 256) {
        int fq = idx & 15;
        float4 s4 = sc[fq], h4 = sh[fq];
        float4 a = *(const float4*)(g_agg + idx * 4);
        float4 p = *(float4*)(g_hprev + idx * 4);
        p.x += fmaxf(fmaf(a.x, s4.x, h4.x), 0.f);
        p.y += fmaxf(fmaf(a.y, s4.y, h4.y), 0.f);
        p.z += fmaxf(fmaf(a.z, s4.z, h4.z), 0.f);
        p.w += fmaxf(fmaf(a.w, s4.w, h4.w), 0.f);
        *(float4*)(g_hprev + idx * 4) = p;
    }
}

// ---------------- output GEMM: out = hprev @ Wo + bo ------------------------
__global__ __launch_bounds__(256) void k_outgemm(const float* __restrict__ Wo,
                                                 const float* __restrict__ bo,
                                                 float* __restrict__ out) {
    __shared__ float Ws[HID * OUTF];  // 10 KB
    __shared__ float bs[OUTF];
    __shared__ float hp[32][HID];     // 8 KB
    int tid = threadIdx.x;
    for (int i = tid; i < HID * OUTF; i += 256) Ws[i] = Wo[i];
    if (tid < OUTF) bs[tid] = bo[tid];
    __syncthreads();
    int rowBase = blockIdx.x * 32;
    for (int i = tid; i < 32 * 16; i += 256) {
        int rr = i >> 4, q = (i & 15) * 4;
        int gr = rowBase + rr;
        float4 v = make_float4(0.f, 0.f, 0.f, 0.f);
        if (gr < Nn) v = *(const float4*)(g_hprev + gr * HID + q);
        *(float4*)(&hp[rr][q]) = v;
    }
    __syncthreads();
    for (int idx = tid; idx < 32 * OUTF; idx += 256) {
        int rr = idx / OUTF, f = idx % OUTF;
        int gr = rowBase + rr;
        if (gr >= Nn) continue;
        float acc = bs[f];
        #pragma unroll
        for (int k = 0; k < HID; k++) acc += hp[rr][k] * Ws[k * OUTF + f];
        out[gr * OUTF + f] = acc;
    }
}

// ---------------- launch ------------------------------------------------------
extern "C" void kernel_launch(void* const* d_in, const int* in_sizes, int n_in,
                              void* d_out, int out_size) {
    const float* x     = (const float*)d_in[0];
    const void*  ei    = d_in[1];
    const float* Wi    = (const float*)d_in[2];
    const float* bi    = (const float*)d_in[3];
    const float* w1    = (const float*)d_in[4];
    const float* w2    = (const float*)d_in[5];
    const float* gamma = (const float*)d_in[6];
    const float* beta  = (const float*)d_in[7];
    const float* Wo    = (const float*)d_in[8];
    const float* bo    = (const float*)d_in[9];
    float* out = (float*)d_out;

    k_detect_zero<<<(Nn + 255) / 256, 256>>>(ei);
    k_deg<<<(Ee + 255) / 256, 256>>>(ei);
    k_dinv_final<<<(Nn + 255) / 256, 256>>>();
    k_prep<<<(Ee + 255) / 256, 256>>>(ei);

    k_ingemm<<<(Nn + 63) / 64, 256>>>(x, Wi, bi);

    for (int l = 0; l < NL; l++) {
        k_layergemm<<<592, 256>>>(w1 + l * HID * HID, w2 + l * HID * HID);
        k_scatter<<<(Ee * 16 + 255) / 256, 256>>>();
        k_combine<<<592, 256>>>();
        k_bnapply<<<592, 256>>>(gamma + l * HID, beta + l * HID);
    }

    k_outgemm<<<(Nn + 31) / 32, 256>>>(Wo, bo, out);
}